// round 7
// baseline (speedup 1.0000x reference)
#include <cuda_runtime.h>
#include <cuda_bf16.h>
#include <math.h>

// Problem constants (shapes fixed by the reference)
#define MAXN 50000
#define MAXE 600000
#define FDIM 128
#define GMAX 64
#define CDIM 2

// ---------------------------------------------------------------------------
// Scratch (static __device__ — no allocation allowed)
// ---------------------------------------------------------------------------
__device__ int   g_cnt [MAXN];          // in-degree (edges only, no self loop)
__device__ int   g_fill[MAXN];          // scatter cursors
__device__ int   g_off [MAXN + 1];      // CSR offsets
__device__ int   g_csr [MAXE];          // CSR src lists (grouped by dst)
__device__ float g_dinv[MAXN];
__device__ float g_Hs  [MAXN * FDIM];   // (A@W) * dinv[row]
__device__ float g_O   [MAXN * FDIM];   // aggregated layer output
__device__ float g_pool[GMAX * FDIM];

// ---------------------------------------------------------------------------
// Helpers
// ---------------------------------------------------------------------------
__device__ __forceinline__ void atomicMaxFloat(float* a, float v) {
    if (v >= 0.f) atomicMax((int*)a, __float_as_int(v));
    else          atomicMin((unsigned int*)a, __float_as_uint(v));
}

// ---------------------------------------------------------------------------
// K1: init counters + pool buffer
// ---------------------------------------------------------------------------
__global__ void init_kernel(int n, int gtot) {
    int i = blockIdx.x * blockDim.x + threadIdx.x;
    if (i < n) { g_cnt[i] = 0; g_fill[i] = 0; }
    if (i < gtot) g_pool[i] = -3.402823466e38f;
}

// K2: in-degree histogram
__global__ void count_kernel(const int* __restrict__ dst, int E) {
    int e = blockIdx.x * blockDim.x + threadIdx.x;
    if (e < E) atomicAdd(&g_cnt[dst[e]], 1);
}

// K3: single-block exclusive scan (n=50000) -> g_off, plus dinv
__global__ void scan_kernel(int n) {
    __shared__ int warpsum[32];
    const int T = 1024;
    int tid = threadIdx.x;
    int chunk = (n + T - 1) / T;
    int s = tid * chunk;
    int e = min(s + chunk, n);
    int sum = 0;
    for (int i = s; i < e; i++) sum += g_cnt[i];

    int lane = tid & 31, wid = tid >> 5;
    int v = sum;
#pragma unroll
    for (int o = 1; o < 32; o <<= 1) {
        int t = __shfl_up_sync(0xffffffffu, v, o);
        if (lane >= o) v += t;
    }
    if (lane == 31) warpsum[wid] = v;
    __syncthreads();
    if (wid == 0) {
        int w = warpsum[lane];
#pragma unroll
        for (int o = 1; o < 32; o <<= 1) {
            int t = __shfl_up_sync(0xffffffffu, w, o);
            if (lane >= o) w += t;
        }
        warpsum[lane] = w;
    }
    __syncthreads();
    int base = (wid > 0 ? warpsum[wid - 1] : 0) + (v - sum);
    int run = base;
    for (int i = s; i < e; i++) {
        int c = g_cnt[i];
        g_off[i] = run;
        g_dinv[i] = rsqrtf((float)(c + 1));   // + self loop
        run += c;
    }
    if (s < n && e == n) g_off[n] = run;
}

// K4: CSR fill
__global__ void scatter_kernel(const int* __restrict__ src,
                               const int* __restrict__ dst, int E) {
    int e = blockIdx.x * blockDim.x + threadIdx.x;
    if (e >= E) return;
    int d = dst[e];
    int pos = atomicAdd(&g_fill[d], 1);
    g_csr[g_off[d] + pos] = src[e];
}

// ---------------------------------------------------------------------------
// K5/K7: SGEMM  Hs = act(A) @ W * dinv[row]   [M x 128] x [128 x 128]
// 128x128 tile, BK=32, 256 threads (8 warps in 2x4), 8x8 micro-tile with
// split rows (r*4..+3 and +32..+35) for conflict-free LDS.128.
// ---------------------------------------------------------------------------
template<bool RELU_A>
__global__ __launch_bounds__(256, 2)
void gemm_gcn(const float* __restrict__ A, const float* __restrict__ W,
              float* __restrict__ Hout, int M)
{
    const int BK = 32;
    __shared__ float As_T[BK][132];   // [k][m], pad 4
    __shared__ float Bs[BK][128];     // [k][n]

    int block_row = blockIdx.x * 128;
    int tid  = threadIdx.x;
    int wid  = tid >> 5;
    int lane = tid & 31;
    int warpRow = wid >> 2;           // 0..1  -> 64 rows
    int warpCol = wid & 3;            // 0..3  -> 32 cols
    int r = lane & 7;                 // 0..7
    int c = lane >> 3;                // 0..3
    int rowb = warpRow * 64 + r * 4;  // thread rows: rowb..+3, rowb+32..+35
    int colb = warpCol * 32 + c * 8;  // thread cols: colb..+7

    float acc[8][8];
#pragma unroll
    for (int i = 0; i < 8; i++)
#pragma unroll
        for (int j = 0; j < 8; j++) acc[i][j] = 0.f;

#pragma unroll
    for (int k0 = 0; k0 < 128; k0 += BK) {
        // A tile (128 rows x 32 k) -> transposed store
#pragma unroll
        for (int i = 0; i < 4; i++) {
            int s  = tid + i * 256;     // 0..1023
            int m  = s >> 3;            // 0..127
            int kk = (s & 7) * 4;       // 0..28
            int gr = block_row + m;
            float4 v = make_float4(0.f, 0.f, 0.f, 0.f);
            if (gr < M) v = *(const float4*)(A + (size_t)gr * FDIM + k0 + kk);
            if (RELU_A) {
                v.x = fmaxf(v.x, 0.f); v.y = fmaxf(v.y, 0.f);
                v.z = fmaxf(v.z, 0.f); v.w = fmaxf(v.w, 0.f);
            }
            As_T[kk + 0][m] = v.x;
            As_T[kk + 1][m] = v.y;
            As_T[kk + 2][m] = v.z;
            As_T[kk + 3][m] = v.w;
        }
        // B tile (32 k x 128 n)
#pragma unroll
        for (int i = 0; i < 4; i++) {
            int s  = tid + i * 256;
            int kk = s >> 5;            // 0..31
            int n4 = (s & 31) * 4;      // 0..124
            *(float4*)&Bs[kk][n4] = *(const float4*)(W + (size_t)(k0 + kk) * FDIM + n4);
        }
        __syncthreads();

#pragma unroll
        for (int k = 0; k < BK; k++) {
            float4 a0 = *(float4*)&As_T[k][rowb];
            float4 a1 = *(float4*)&As_T[k][rowb + 32];
            float4 b0 = *(float4*)&Bs[k][colb];
            float4 b1 = *(float4*)&Bs[k][colb + 4];
            float a[8] = {a0.x, a0.y, a0.z, a0.w, a1.x, a1.y, a1.z, a1.w};
            float b[8] = {b0.x, b0.y, b0.z, b0.w, b1.x, b1.y, b1.z, b1.w};
#pragma unroll
            for (int i = 0; i < 8; i++)
#pragma unroll
                for (int j = 0; j < 8; j++) acc[i][j] += a[i] * b[j];
        }
        __syncthreads();
    }

    // epilogue: Hs = acc * dinv[row]
#pragma unroll
    for (int i = 0; i < 8; i++) {
        int gr = block_row + rowb + (i < 4 ? i : 28 + i);  // i>=4 -> +32+(i-4)
        if (gr >= M) continue;
        float dv = g_dinv[gr];
        float4 o0 = make_float4(acc[i][0] * dv, acc[i][1] * dv,
                                acc[i][2] * dv, acc[i][3] * dv);
        float4 o1 = make_float4(acc[i][4] * dv, acc[i][5] * dv,
                                acc[i][6] * dv, acc[i][7] * dv);
        *(float4*)(Hout + (size_t)gr * FDIM + colb)     = o0;
        *(float4*)(Hout + (size_t)gr * FDIM + colb + 4) = o1;
    }
}

// ---------------------------------------------------------------------------
// K6/K8: CSR gather aggregation. One warp per dst node:
//   O[d] = dinv[d] * (Hs[d] + sum_{s in N(d)} Hs[s]) + bias
// Each lane owns one float4 (lane*4 .. lane*4+3) of the 128-wide row.
// ---------------------------------------------------------------------------
__global__ __launch_bounds__(256)
void agg_kernel(const float* __restrict__ bias, int N)
{
    int node = (blockIdx.x * blockDim.x + threadIdx.x) >> 5;
    if (node >= N) return;
    int lane = threadIdx.x & 31;

    const float4* Hrow = (const float4*)(g_Hs + (size_t)node * FDIM);
    float4 acc = Hrow[lane];                       // self contribution
    int beg = __ldg(&g_off[node]);
    int end = __ldg(&g_off[node + 1]);
    for (int j = beg; j < end; j++) {
        int s = __ldg(&g_csr[j]);
        float4 v = *(const float4*)(g_Hs + (size_t)s * FDIM + lane * 4);
        acc.x += v.x; acc.y += v.y; acc.z += v.z; acc.w += v.w;
    }
    float dv = g_dinv[node];
    float4 bv = *(const float4*)(bias + lane * 4);
    float4 o = make_float4(acc.x * dv + bv.x, acc.y * dv + bv.y,
                           acc.z * dv + bv.z, acc.w * dv + bv.w);
    *(float4*)(g_O + (size_t)node * FDIM + lane * 4) = o;
}

// ---------------------------------------------------------------------------
// K9: segment max pool over sorted batch ids
// ---------------------------------------------------------------------------
#define POOL_NODES 256
__global__ void pool_kernel(const int* __restrict__ batch, int M)
{
    int j  = threadIdx.x;
    int n0 = blockIdx.x * POOL_NODES;
    int n1 = min(n0 + POOL_NODES, M);
    if (n0 >= M) return;
    int cur = __ldg(&batch[n0]);
    float m = -3.402823466e38f;
    for (int i = n0; i < n1; i++) {
        int b = __ldg(&batch[i]);
        if (b != cur) {
            atomicMaxFloat(&g_pool[cur * FDIM + j], m);
            cur = b;
            m = -3.402823466e38f;
        }
        m = fmaxf(m, g_O[(size_t)i * FDIM + j]);
    }
    atomicMaxFloat(&g_pool[cur * FDIM + j], m);
}

// ---------------------------------------------------------------------------
// K10: MLP head, one block per graph (128 threads)
// ---------------------------------------------------------------------------
__global__ void mlp_kernel(const float* __restrict__ Wl1, const float* __restrict__ bl1,
                           const float* __restrict__ Wl2, const float* __restrict__ bl2,
                           const float* __restrict__ Wo,  const float* __restrict__ bo,
                           float* __restrict__ out)
{
    __shared__ float gv[128], t1[128], t2[128], logits[CDIM];
    int g = blockIdx.x, j = threadIdx.x;

    gv[j] = g_pool[g * FDIM + j];
    __syncthreads();

    float acc = bl1[j];
#pragma unroll 8
    for (int k = 0; k < 128; k++) acc += gv[k] * Wl1[k * 128 + j];
    t1[j] = fmaxf(acc, 0.f);
    __syncthreads();

    acc = bl2[j];
#pragma unroll 8
    for (int k = 0; k < 128; k++) acc += t1[k] * Wl2[k * 128 + j];
    t2[j] = fmaxf(acc, 0.f);
    __syncthreads();

    if (j < CDIM) {
        float l = bo[j];
#pragma unroll 8
        for (int k = 0; k < 128; k++) l += t2[k] * Wo[k * CDIM + j];
        logits[j] = l;
    }
    __syncthreads();

    if (j < CDIM) {
        float m = fmaxf(logits[0], logits[1]);
        float e = expf(logits[j] - m);
        float s = expf(logits[0] - m) + expf(logits[1] - m);
        out[g * CDIM + j] = e / s;
    }
}

// ---------------------------------------------------------------------------
// Launch: 0:x 1:edge_index 2:batch 3:W1 4:b1 5:W2 6:b2 7:Wl1 8:bl1 9:Wl2
//         10:bl2 11:Wo 12:bo
// ---------------------------------------------------------------------------
extern "C" void kernel_launch(void* const* d_in, const int* in_sizes, int n_in,
                              void* d_out, int out_size)
{
    const float* x    = (const float*)d_in[0];
    const int*   ei   = (const int*)  d_in[1];
    const int*   batch= (const int*)  d_in[2];
    const float* W1   = (const float*)d_in[3];
    const float* b1   = (const float*)d_in[4];
    const float* W2   = (const float*)d_in[5];
    const float* b2   = (const float*)d_in[6];
    const float* Wl1  = (const float*)d_in[7];
    const float* bl1  = (const float*)d_in[8];
    const float* Wl2  = (const float*)d_in[9];
    const float* bl2  = (const float*)d_in[10];
    const float* Wo   = (const float*)d_in[11];
    const float* bo   = (const float*)d_in[12];
    float* out = (float*)d_out;

    int N = in_sizes[0] / FDIM;        // 50000
    int E = in_sizes[1] / 2;           // 600000
    int G = out_size / CDIM;           // 64
    const int* src = ei;               // edge_index[0]
    const int* dst = ei + E;           // edge_index[1]

    float *Hp, *Op;
    cudaGetSymbolAddress((void**)&Hp, g_Hs);
    cudaGetSymbolAddress((void**)&Op, g_O);

    // --- CSR build ---
    int initN = (N > G * FDIM) ? N : G * FDIM;
    init_kernel<<<(initN + 255) / 256, 256>>>(N, G * FDIM);
    count_kernel<<<(E + 255) / 256, 256>>>(dst, E);
    scan_kernel<<<1, 1024>>>(N);
    scatter_kernel<<<(E + 255) / 256, 256>>>(src, dst, E);

    int gemm_blocks = (N + 127) / 128;
    int agg_blocks  = (int)(((long long)N * 32 + 255) / 256);

    // layer 1
    gemm_gcn<false><<<gemm_blocks, 256>>>(x, W1, Hp, N);
    agg_kernel<<<agg_blocks, 256>>>(b1, N);
    // layer 2 (relu fused into A-load)
    gemm_gcn<true><<<gemm_blocks, 256>>>(Op, W2, Hp, N);
    agg_kernel<<<agg_blocks, 256>>>(b2, N);

    pool_kernel<<<(N + POOL_NODES - 1) / POOL_NODES, 128>>>(batch, N);
    mlp_kernel<<<G, 128>>>(Wl1, bl1, Wl2, bl2, Wo, bo, out);
}

// round 8
// speedup vs baseline: 1.0313x; 1.0313x over previous
#include <cuda_runtime.h>
#include <cuda_bf16.h>
#include <math.h>

// Problem constants (shapes fixed by the reference)
#define MAXN 50000
#define MAXE 600000
#define FDIM 128
#define GMAX 64
#define CDIM 2

// ---------------------------------------------------------------------------
// Scratch (static __device__ — no allocation allowed)
// ---------------------------------------------------------------------------
__device__ int   g_cnt [MAXN];          // in-degree (edges only, no self loop)
__device__ int   g_fill[MAXN];          // scatter cursors
__device__ int   g_off [MAXN + 1];      // CSR offsets
__device__ int   g_bsum[256];           // per-block sums for scan
__device__ int   g_csr [MAXE];          // CSR src lists (grouped by dst)
__device__ float g_dinv[MAXN];
__device__ float g_Hs  [MAXN * FDIM];   // (A@W) * dinv[row]
__device__ float g_O   [MAXN * FDIM];   // aggregated layer output
__device__ float g_pool[GMAX * FDIM];

// ---------------------------------------------------------------------------
// Helpers
// ---------------------------------------------------------------------------
__device__ __forceinline__ void atomicMaxFloat(float* a, float v) {
    if (v >= 0.f) atomicMax((int*)a, __float_as_int(v));
    else          atomicMin((unsigned int*)a, __float_as_uint(v));
}

// ---------------------------------------------------------------------------
// K1: init counters + pool buffer
// ---------------------------------------------------------------------------
__global__ void init_kernel(int n, int gtot) {
    int i = blockIdx.x * blockDim.x + threadIdx.x;
    if (i < n) { g_cnt[i] = 0; g_fill[i] = 0; }
    if (i < gtot) g_pool[i] = -3.402823466e38f;
}

// K2: in-degree histogram
__global__ void count_kernel(const int* __restrict__ dst, int E) {
    int e = blockIdx.x * blockDim.x + threadIdx.x;
    if (e < E) atomicAdd(&g_cnt[dst[e]], 1);
}

// ---------------------------------------------------------------------------
// K3a: per-block sums of g_cnt (256 elems per block, coalesced)
// ---------------------------------------------------------------------------
__global__ void bsum_kernel(int n) {
    int i = blockIdx.x * 256 + threadIdx.x;
    int v = (i < n) ? g_cnt[i] : 0;
#pragma unroll
    for (int o = 16; o; o >>= 1) v += __shfl_down_sync(0xffffffffu, v, o);
    __shared__ int ws[8];
    if ((threadIdx.x & 31) == 0) ws[threadIdx.x >> 5] = v;
    __syncthreads();
    if (threadIdx.x < 8) {
        int s = ws[threadIdx.x];
#pragma unroll
        for (int o = 4; o; o >>= 1) s += __shfl_down_sync(0xffu, s, o);
        if (threadIdx.x == 0) g_bsum[blockIdx.x] = s;
    }
}

// K3b: single-block exclusive scan of nb (<=256) block sums
__global__ void bscan_kernel(int nb) {
    int t = threadIdx.x;
    int v = (t < nb) ? g_bsum[t] : 0;
    int lane = t & 31, w = t >> 5;
    int x = v;
#pragma unroll
    for (int o = 1; o < 32; o <<= 1) {
        int y = __shfl_up_sync(0xffffffffu, x, o);
        if (lane >= o) x += y;
    }
    __shared__ int ws[8];
    if (lane == 31) ws[w] = x;
    __syncthreads();
    if (t < 8) {
        int s = ws[t];
#pragma unroll
        for (int o = 1; o < 8; o <<= 1) {
            int y = __shfl_up_sync(0xffu, s, o);
            if (t >= o) s += y;
        }
        ws[t] = s;
    }
    __syncthreads();
    int incl = x + (w ? ws[w - 1] : 0);
    if (t < nb) g_bsum[t] = incl - v;   // exclusive prefix
}

// K3c: per-block exclusive scan + global base -> g_off, plus dinv
__global__ void fill_kernel(int n) {
    int i = blockIdx.x * 256 + threadIdx.x;
    int c = (i < n) ? g_cnt[i] : 0;
    int lane = threadIdx.x & 31, w = threadIdx.x >> 5;
    int x = c;
#pragma unroll
    for (int o = 1; o < 32; o <<= 1) {
        int y = __shfl_up_sync(0xffffffffu, x, o);
        if (lane >= o) x += y;
    }
    __shared__ int ws[8];
    if (lane == 31) ws[w] = x;
    __syncthreads();
    if (threadIdx.x < 8) {
        int s = ws[threadIdx.x];
#pragma unroll
        for (int o = 1; o < 8; o <<= 1) {
            int y = __shfl_up_sync(0xffu, s, o);
            if (threadIdx.x >= o) s += y;
        }
        ws[threadIdx.x] = s;
    }
    __syncthreads();
    int excl = x - c + (w ? ws[w - 1] : 0);
    int off = g_bsum[blockIdx.x] + excl;
    if (i < n) {
        g_off[i]  = off;
        g_dinv[i] = rsqrtf((float)(c + 1));   // + self loop
        if (i == n - 1) g_off[n] = off + c;
    }
}

// K4: CSR fill
__global__ void scatter_kernel(const int* __restrict__ src,
                               const int* __restrict__ dst, int E) {
    int e = blockIdx.x * blockDim.x + threadIdx.x;
    if (e >= E) return;
    int d = dst[e];
    int pos = atomicAdd(&g_fill[d], 1);
    g_csr[g_off[d] + pos] = src[e];
}

// ---------------------------------------------------------------------------
// K5/K7: SGEMM  Hs = act(A) @ W * dinv[row]   [M x 128] x [128 x 128]
// 128x128 tile, BK=32, 256 threads (8 warps in 2x4), 8x8 micro-tile with
// split rows for conflict-free LDS.128.
// ---------------------------------------------------------------------------
template<bool RELU_A>
__global__ __launch_bounds__(256, 2)
void gemm_gcn(const float* __restrict__ A, const float* __restrict__ W,
              float* __restrict__ Hout, int M)
{
    const int BK = 32;
    __shared__ float As_T[BK][132];   // [k][m], pad 4
    __shared__ float Bs[BK][128];     // [k][n]

    int block_row = blockIdx.x * 128;
    int tid  = threadIdx.x;
    int wid  = tid >> 5;
    int lane = tid & 31;
    int warpRow = wid >> 2;           // 0..1  -> 64 rows
    int warpCol = wid & 3;            // 0..3  -> 32 cols
    int r = lane & 7;                 // 0..7
    int c = lane >> 3;                // 0..3
    int rowb = warpRow * 64 + r * 4;  // thread rows: rowb..+3, rowb+32..+35
    int colb = warpCol * 32 + c * 8;  // thread cols: colb..+7

    float acc[8][8];
#pragma unroll
    for (int i = 0; i < 8; i++)
#pragma unroll
        for (int j = 0; j < 8; j++) acc[i][j] = 0.f;

#pragma unroll
    for (int k0 = 0; k0 < 128; k0 += BK) {
        // A tile (128 rows x 32 k) -> transposed store
#pragma unroll
        for (int i = 0; i < 4; i++) {
            int s  = tid + i * 256;     // 0..1023
            int m  = s >> 3;            // 0..127
            int kk = (s & 7) * 4;       // 0..28
            int gr = block_row + m;
            float4 v = make_float4(0.f, 0.f, 0.f, 0.f);
            if (gr < M) v = *(const float4*)(A + (size_t)gr * FDIM + k0 + kk);
            if (RELU_A) {
                v.x = fmaxf(v.x, 0.f); v.y = fmaxf(v.y, 0.f);
                v.z = fmaxf(v.z, 0.f); v.w = fmaxf(v.w, 0.f);
            }
            As_T[kk + 0][m] = v.x;
            As_T[kk + 1][m] = v.y;
            As_T[kk + 2][m] = v.z;
            As_T[kk + 3][m] = v.w;
        }
        // B tile (32 k x 128 n)
#pragma unroll
        for (int i = 0; i < 4; i++) {
            int s  = tid + i * 256;
            int kk = s >> 5;            // 0..31
            int n4 = (s & 31) * 4;      // 0..124
            *(float4*)&Bs[kk][n4] = *(const float4*)(W + (size_t)(k0 + kk) * FDIM + n4);
        }
        __syncthreads();

#pragma unroll
        for (int k = 0; k < BK; k++) {
            float4 a0 = *(float4*)&As_T[k][rowb];
            float4 a1 = *(float4*)&As_T[k][rowb + 32];
            float4 b0 = *(float4*)&Bs[k][colb];
            float4 b1 = *(float4*)&Bs[k][colb + 4];
            float a[8] = {a0.x, a0.y, a0.z, a0.w, a1.x, a1.y, a1.z, a1.w};
            float b[8] = {b0.x, b0.y, b0.z, b0.w, b1.x, b1.y, b1.z, b1.w};
#pragma unroll
            for (int i = 0; i < 8; i++)
#pragma unroll
                for (int j = 0; j < 8; j++) acc[i][j] += a[i] * b[j];
        }
        __syncthreads();
    }

    // epilogue: Hs = acc * dinv[row]
#pragma unroll
    for (int i = 0; i < 8; i++) {
        int gr = block_row + rowb + (i < 4 ? i : 28 + i);  // i>=4 -> +32+(i-4)
        if (gr >= M) continue;
        float dv = g_dinv[gr];
        float4 o0 = make_float4(acc[i][0] * dv, acc[i][1] * dv,
                                acc[i][2] * dv, acc[i][3] * dv);
        float4 o1 = make_float4(acc[i][4] * dv, acc[i][5] * dv,
                                acc[i][6] * dv, acc[i][7] * dv);
        *(float4*)(Hout + (size_t)gr * FDIM + colb)     = o0;
        *(float4*)(Hout + (size_t)gr * FDIM + colb + 4) = o1;
    }
}

// ---------------------------------------------------------------------------
// K6/K8: CSR gather aggregation. FOUR warps per dst node; each warp owns a
// 32-float quarter of the row (lane = one float -> 128B coalesced per edge).
// 4-way unrolled so each warp keeps ~4 row-reads in flight.
//   O[d] = dinv[d] * (Hs[d] + sum_{s in N(d)} Hs[s]) + bias
// ---------------------------------------------------------------------------
__global__ __launch_bounds__(256)
void agg_kernel(const float* __restrict__ bias, int N)
{
    int gw   = (blockIdx.x * blockDim.x + threadIdx.x) >> 5;
    int node = gw >> 2;
    if (node >= N) return;
    int col  = ((gw & 3) << 5) | (threadIdx.x & 31);

    const float* __restrict__ H = g_Hs;
    float self = __ldg(&H[(size_t)node * FDIM + col]);
    int beg = __ldg(&g_off[node]);
    int end = __ldg(&g_off[node + 1]);

    float a0 = 0.f, a1 = 0.f, a2 = 0.f, a3 = 0.f;
    int j = beg;
    for (; j + 4 <= end; j += 4) {
        int s0 = __ldg(&g_csr[j + 0]);
        int s1 = __ldg(&g_csr[j + 1]);
        int s2 = __ldg(&g_csr[j + 2]);
        int s3 = __ldg(&g_csr[j + 3]);
        a0 += __ldg(&H[(size_t)s0 * FDIM + col]);
        a1 += __ldg(&H[(size_t)s1 * FDIM + col]);
        a2 += __ldg(&H[(size_t)s2 * FDIM + col]);
        a3 += __ldg(&H[(size_t)s3 * FDIM + col]);
    }
    for (; j < end; j++) {
        int s = __ldg(&g_csr[j]);
        a0 += __ldg(&H[(size_t)s * FDIM + col]);
    }
    float acc = self + ((a0 + a1) + (a2 + a3));
    g_O[(size_t)node * FDIM + col] = acc * g_dinv[node] + __ldg(&bias[col]);
}

// ---------------------------------------------------------------------------
// K9: segment max pool over sorted batch ids
// ---------------------------------------------------------------------------
#define POOL_NODES 256
__global__ void pool_kernel(const int* __restrict__ batch, int M)
{
    int j  = threadIdx.x;
    int n0 = blockIdx.x * POOL_NODES;
    int n1 = min(n0 + POOL_NODES, M);
    if (n0 >= M) return;
    int cur = __ldg(&batch[n0]);
    float m = -3.402823466e38f;
    for (int i = n0; i < n1; i++) {
        int b = __ldg(&batch[i]);
        if (b != cur) {
            atomicMaxFloat(&g_pool[cur * FDIM + j], m);
            cur = b;
            m = -3.402823466e38f;
        }
        m = fmaxf(m, g_O[(size_t)i * FDIM + j]);
    }
    atomicMaxFloat(&g_pool[cur * FDIM + j], m);
}

// ---------------------------------------------------------------------------
// K10: MLP head, one block per graph (128 threads)
// ---------------------------------------------------------------------------
__global__ void mlp_kernel(const float* __restrict__ Wl1, const float* __restrict__ bl1,
                           const float* __restrict__ Wl2, const float* __restrict__ bl2,
                           const float* __restrict__ Wo,  const float* __restrict__ bo,
                           float* __restrict__ out)
{
    __shared__ float gv[128], t1[128], t2[128], logits[CDIM];
    int g = blockIdx.x, j = threadIdx.x;

    gv[j] = g_pool[g * FDIM + j];
    __syncthreads();

    float acc = bl1[j];
#pragma unroll 8
    for (int k = 0; k < 128; k++) acc += gv[k] * Wl1[k * 128 + j];
    t1[j] = fmaxf(acc, 0.f);
    __syncthreads();

    acc = bl2[j];
#pragma unroll 8
    for (int k = 0; k < 128; k++) acc += t1[k] * Wl2[k * 128 + j];
    t2[j] = fmaxf(acc, 0.f);
    __syncthreads();

    if (j < CDIM) {
        float l = bo[j];
#pragma unroll 8
        for (int k = 0; k < 128; k++) l += t2[k] * Wo[k * CDIM + j];
        logits[j] = l;
    }
    __syncthreads();

    if (j < CDIM) {
        float m = fmaxf(logits[0], logits[1]);
        float e = expf(logits[j] - m);
        float s = expf(logits[0] - m) + expf(logits[1] - m);
        out[g * CDIM + j] = e / s;
    }
}

// ---------------------------------------------------------------------------
// Launch: 0:x 1:edge_index 2:batch 3:W1 4:b1 5:W2 6:b2 7:Wl1 8:bl1 9:Wl2
//         10:bl2 11:Wo 12:bo
// ---------------------------------------------------------------------------
extern "C" void kernel_launch(void* const* d_in, const int* in_sizes, int n_in,
                              void* d_out, int out_size)
{
    const float* x    = (const float*)d_in[0];
    const int*   ei   = (const int*)  d_in[1];
    const int*   batch= (const int*)  d_in[2];
    const float* W1   = (const float*)d_in[3];
    const float* b1   = (const float*)d_in[4];
    const float* W2   = (const float*)d_in[5];
    const float* b2   = (const float*)d_in[6];
    const float* Wl1  = (const float*)d_in[7];
    const float* bl1  = (const float*)d_in[8];
    const float* Wl2  = (const float*)d_in[9];
    const float* bl2  = (const float*)d_in[10];
    const float* Wo   = (const float*)d_in[11];
    const float* bo   = (const float*)d_in[12];
    float* out = (float*)d_out;

    int N = in_sizes[0] / FDIM;        // 50000
    int E = in_sizes[1] / 2;           // 600000
    int G = out_size / CDIM;           // 64
    const int* src = ei;               // edge_index[0]
    const int* dst = ei + E;           // edge_index[1]

    float *Hp, *Op;
    cudaGetSymbolAddress((void**)&Hp, g_Hs);
    cudaGetSymbolAddress((void**)&Op, g_O);

    // --- CSR build ---
    int initN = (N > G * FDIM) ? N : G * FDIM;
    int nb = (N + 255) / 256;          // 196 scan blocks
    init_kernel<<<(initN + 255) / 256, 256>>>(N, G * FDIM);
    count_kernel<<<(E + 255) / 256, 256>>>(dst, E);
    bsum_kernel<<<nb, 256>>>(N);
    bscan_kernel<<<1, 256>>>(nb);
    fill_kernel<<<nb, 256>>>(N);
    scatter_kernel<<<(E + 255) / 256, 256>>>(src, dst, E);

    int gemm_blocks = (N + 127) / 128;
    int agg_blocks  = (int)(((long long)N * 4 * 32 + 255) / 256);  // 4 warps/node

    // layer 1
    gemm_gcn<false><<<gemm_blocks, 256>>>(x, W1, Hp, N);
    agg_kernel<<<agg_blocks, 256>>>(b1, N);
    // layer 2 (relu fused into A-load)
    gemm_gcn<true><<<gemm_blocks, 256>>>(Op, W2, Hp, N);
    agg_kernel<<<agg_blocks, 256>>>(b2, N);

    pool_kernel<<<(N + POOL_NODES - 1) / POOL_NODES, 128>>>(batch, N);
    mlp_kernel<<<G, 128>>>(Wl1, bl1, Wl2, bl2, Wo, bo, out);
}